// round 8
// baseline (speedup 1.0000x reference)
#include <cuda_runtime.h>
#include <cstdint>

#define NB      32768
#define IN_DIM  2048
#define OUT_DIM 2432

#define C_INV3 0.57735026918962576451f
#define C_INV5 0.44721359549995793928f
#define C_INV7 0.37796447300922722721f

// Scratch for mode-1 mixed factors: [NB][384], pre-scaled by 1/sqrt(d).
__device__ float g_mixed[(size_t)NB * 384];

// ---------------- tf32 mma.sync helpers (base sm_103) ----------------
__device__ __forceinline__ uint32_t cvt_tf32(float x) {
    uint32_t r; asm("cvt.rna.tf32.f32 %0, %1;" : "=r"(r) : "f"(x)); return r;
}
__device__ __forceinline__ void mma_tf32_v(float c[4], uint4 a,
                                           uint32_t b0, uint32_t b1) {
    asm volatile(
        "mma.sync.aligned.m16n8k8.row.col.f32.tf32.tf32.f32 "
        "{%0,%1,%2,%3}, {%4,%5,%6,%7}, {%8,%9}, {%0,%1,%2,%3};"
        : "+f"(c[0]), "+f"(c[1]), "+f"(c[2]), "+f"(c[3])
        : "r"(a.x), "r"(a.y), "r"(a.z), "r"(a.w), "r"(b0), "r"(b1));
}
__device__ __forceinline__ void bar_g(int id) {
    asm volatile("bar.sync %0, 128;" :: "r"(id) : "memory");
}
// paired column index: (v, v+4) adjacent -> LDS.64 B-fragments
__device__ __forceinline__ int pcol(int v) {
    return ((v >> 3) << 3) + ((v & 3) << 1) + ((v >> 2) & 1);
}

// ---------------------------------------------------------------------------
// mode-1 GEMM: g_mixed[b, u'] = sum_v x2[b,v] * W'[u',v] * scale(u')
//   A = x2 tile, stored FRAG-MAJOR (one LDS.128 per A-fragment)
//   B = stacked scaled W' [384][136] with paired columns (LDS.64 frags)
// ---------------------------------------------------------------------------
__global__ void __launch_bounds__(256, 1)
mode1_mma(const float* __restrict__ x2, const float* __restrict__ weight)
{
    extern __shared__ uint32_t smu[];
    uint32_t* Wp = smu;                     // [384][136] paired
    uint32_t* Af = smu + 384 * 136;         // [16 s][32 lane][4] frag-major

    const int tid  = threadIdx.x;
    const int lane = tid & 31;
    const int warp = tid >> 5;
    const int gid  = lane >> 2;
    const int tig  = lane & 3;

    // Build W' (scaled, tf32, paired cols). Once.
    for (int f = tid; f < 384 * 32; f += 256) {
        int u = f >> 5, q = f & 31;
        int p = u >> 7;
        float sc = (p == 0) ? C_INV3 : ((p == 1) ? C_INV5 : C_INV7);
        float4 w4 = ((const float4*)(weight + 4 * 16384))[f];
        float c[4] = {w4.x * sc, w4.y * sc, w4.z * sc, w4.w * sc};
        #pragma unroll
        for (int j = 0; j < 4; j++)
            Wp[u * 136 + pcol(4 * q + j)] = cvt_tf32(c[j]);
    }
    __syncthreads();

    const int n_base = warp * 48;

    for (int s = blockIdx.x; s < NB / 16; s += gridDim.x) {
        const int b0 = s * 16;
        // Build A tile frag-major.
        for (int f = tid; f < 16 * 32; f += 256) {
            int t = f >> 5, q = f & 31;
            float4 v4 = ((const float4*)(x2 + (size_t)(b0 + t) * IN_DIM))[q];
            float c[4] = {v4.x, v4.y, v4.z, v4.w};
            int st  = q >> 1, hi = q & 1;
            int sel = (t >> 3) & 1, g8 = t & 7;
            #pragma unroll
            for (int j = 0; j < 4; j++)
                Af[((st * 32) + g8 * 4 + j) * 4 + sel + 2 * hi] = cvt_tf32(c[j]);
        }
        __syncthreads();

        float acc[6][4];
        #pragma unroll
        for (int nt = 0; nt < 6; nt++)
            #pragma unroll
            for (int j = 0; j < 4; j++) acc[nt][j] = 0.0f;

        #pragma unroll
        for (int s16 = 0; s16 < 16; s16++) {
            uint4 af = *(const uint4*)(Af + (s16 * 32 + lane) * 4);
            #pragma unroll
            for (int nt = 0; nt < 6; nt++) {
                int ur = n_base + nt * 8 + gid;
                uint2 bp = *(const uint2*)(Wp + ur * 136 + s16 * 8 + tig * 2);
                mma_tf32_v(acc[nt], af, bp.x, bp.y);
            }
        }

        // Dump straight to gmem: c0,c1 -> row b0+gid; c2,c3 -> row b0+gid+8.
        #pragma unroll
        for (int nt = 0; nt < 6; nt++) {
            int n0 = n_base + nt * 8 + 2 * tig;
            float2 lo; lo.x = acc[nt][0]; lo.y = acc[nt][1];
            float2 hi; hi.x = acc[nt][2]; hi.y = acc[nt][3];
            *(float2*)(g_mixed + (size_t)(b0 + gid    ) * 384 + n0) = lo;
            *(float2*)(g_mixed + (size_t)(b0 + gid + 8) * 384 + n0) = hi;
        }
        __syncthreads();   // A-tile reads done before next build
    }
}

// ---------------------------------------------------------------------------
// tc_group: 512 threads = 4 independent 128-thread pipelines (named barriers).
// GEMM per 8-row subtile: tmp[u, n=t*D+k] = sum_v W[u,v]*x2[b0+t, in2s+v*D+k].
// W stored frag-major (LDS.128 A-frags); B paired-column pitch 136 (LDS.64);
// B buffer aliased with the accumulator dump Ts[n][u].
// ---------------------------------------------------------------------------
template<int D, bool HAS_M1>
__global__ void __launch_bounds__(512, 1)
tc_group(const float* __restrict__ x1, const float* __restrict__ x2,
         const float* __restrict__ weight, const float* __restrict__ mask,
         float* __restrict__ out,
         int in1s, int in2s, int outs0, int outs1, int ws0, int moff,
         float inv_d)
{
    constexpr int NROW = 8 * D;
    constexpr int PB   = 136;

    extern __shared__ uint32_t smu[];
    uint32_t* Wf = smu;                                 // [8 mt][16 s][32][4]

    const int tid  = threadIdx.x;
    const int g    = tid >> 7;
    const int gt   = tid & 127;
    const int lane = tid & 31;
    const int wg   = (tid >> 5) & 3;
    const int gid  = lane >> 2;
    const int tig  = lane & 3;
    const int bar  = g + 1;

    uint32_t* BTu = smu + 128 * 128 + g * (NROW * PB);  // aliased B / Ts
    float*    BT  = (float*)BTu;

    // Build W frag-major (tf32). Once, all 512 threads.
    for (int f = tid; f < 128 * 32; f += 512) {
        int u = f >> 5, q = f & 31;
        float4 w4 = ((const float4*)(weight + ws0))[f];
        float c[4] = {w4.x, w4.y, w4.z, w4.w};
        int st  = q >> 1, hi = q & 1;
        int mt8 = u >> 4, sel = (u >> 3) & 1, g8 = u & 7;
        #pragma unroll
        for (int j = 0; j < 4; j++)
            Wf[((mt8 * 16 + st) * 32 + g8 * 4 + j) * 4 + sel + 2 * hi] =
                cvt_tf32(c[j]);
    }
    __syncthreads();

    for (int s = blockIdx.x * 4 + g; s < NB / 8; s += gridDim.x * 4) {
        const int b0 = s * 8;

        // ---- build B: BTu[t*D+k][pcol(v)] = tf32(x2[b0+t, in2s + v*D + k]) ----
        for (int f = gt; f < 256 * D; f += 128) {
            int t = f / (32 * D);
            int q = f - t * (32 * D);
            float4 v4 = ((const float4*)(x2 + (size_t)(b0 + t) * IN_DIM + in2s))[q];
            float c[4] = {v4.x, v4.y, v4.z, v4.w};
            int e = 4 * q;
            #pragma unroll
            for (int j = 0; j < 4; j++) {
                int v = (e + j) / D, k = (e + j) % D;
                BTu[(t * D + k) * PB + pcol(v)] = cvt_tf32(c[j]);
            }
        }
        bar_g(bar);

        // ---- MMA: 16 K-steps of k=8 ----
        float acc[2][D][4];
        #pragma unroll
        for (int mt = 0; mt < 2; mt++)
            #pragma unroll
            for (int nt = 0; nt < D; nt++)
                #pragma unroll
                for (int j = 0; j < 4; j++) acc[mt][nt][j] = 0.0f;

        #pragma unroll
        for (int s16 = 0; s16 < 16; s16++) {
            uint4 af0 = *(const uint4*)(Wf + (((wg * 2 + 0) * 16 + s16) * 32 + lane) * 4);
            uint4 af1 = *(const uint4*)(Wf + (((wg * 2 + 1) * 16 + s16) * 32 + lane) * 4);
            #pragma unroll
            for (int nt = 0; nt < D; nt++) {
                uint2 bp = *(const uint2*)(BTu + (nt * 8 + gid) * PB + s16 * 8 + tig * 2);
                mma_tf32_v(acc[0][nt], af0, bp.x, bp.y);
                mma_tf32_v(acc[1][nt], af1, bp.x, bp.y);
            }
        }
        bar_g(bar);          // all 4 warps done reading B

        // ---- dump accums into the same buffer as Ts[n][u] ----
        #pragma unroll
        for (int mt = 0; mt < 2; mt++) {
            int ub = wg * 32 + mt * 16 + gid;
            #pragma unroll
            for (int nt = 0; nt < D; nt++) {
                int n0 = nt * 8 + 2 * tig;
                BT[(n0    ) * PB + ub    ] = acc[mt][nt][0];
                BT[(n0 + 1) * PB + ub    ] = acc[mt][nt][1];
                BT[(n0    ) * PB + ub + 8] = acc[mt][nt][2];
                BT[(n0 + 1) * PB + ub + 8] = acc[mt][nt][3];
            }
        }
        bar_g(bar);

        // ---- vectorized epilogue: warp wg handles t = p*4+wg, lane owns 4u ----
        #pragma unroll
        for (int p = 0; p < 2; p++) {
            const int t = p * 4 + wg;
            const size_t b = (size_t)(b0 + t);

            float xv[4 * D];       // xv[uj*D + k]
            float tv[4 * D];       // tv[k*4 + uj]
            const float4* x1p =
                (const float4*)(x1 + b * IN_DIM + in1s + (size_t)4 * lane * D);
            #pragma unroll
            for (int q = 0; q < D; q++) {
                float4 t4 = __ldg(x1p + q);
                xv[4 * q + 0] = t4.x; xv[4 * q + 1] = t4.y;
                xv[4 * q + 2] = t4.z; xv[4 * q + 3] = t4.w;
            }
            #pragma unroll
            for (int k = 0; k < D; k++) {
                float4 t4 = *(const float4*)(BT + (t * D + k) * PB + 4 * lane);
                tv[4 * k + 0] = t4.x; tv[4 * k + 1] = t4.y;
                tv[4 * k + 2] = t4.z; tv[4 * k + 3] = t4.w;
            }

            float m4[4] = {0.0f, 0.0f, 0.0f, 0.0f};
            #pragma unroll
            for (int uj = 0; uj < 4; uj++)
                #pragma unroll
                for (int k = 0; k < D; k++)
                    m4[uj] = fmaf(xv[uj * D + k], tv[4 * k + uj], m4[uj]);

            {
                float4 mk = __ldg((const float4*)(mask + outs0) + lane);
                float4 o;
                o.x = m4[0] * inv_d * mk.x; o.y = m4[1] * inv_d * mk.y;
                o.z = m4[2] * inv_d * mk.z; o.w = m4[3] * inv_d * mk.w;
                *(float4*)(out + b * OUT_DIM + outs0 + 4 * lane) = o;
            }

            if (HAS_M1) {
                float4 mx = __ldg((const float4*)(g_mixed + b * 384 + moff) + lane);
                float mix[4] = {mx.x, mx.y, mx.z, mx.w};
                const float4* mk1 =
                    (const float4*)(mask + outs1 + (size_t)4 * lane * D);
                float4* op = (float4*)(out + b * OUT_DIM + outs1 + (size_t)4 * lane * D);
                #pragma unroll
                for (int q = 0; q < D; q++) {
                    float4 mq = __ldg(mk1 + q);
                    float4 o;
                    o.x = xv[4 * q + 0] * mix[(4 * q + 0) / D] * mq.x;
                    o.y = xv[4 * q + 1] * mix[(4 * q + 1) / D] * mq.y;
                    o.z = xv[4 * q + 2] * mix[(4 * q + 2) / D] * mq.z;
                    o.w = xv[4 * q + 3] * mix[(4 * q + 3) / D] * mq.w;
                    op[q] = o;
                }
            }
        }
        bar_g(bar);          // Ts reads done before next build overwrites
    }
}

// ---------------------------------------------------------------------------
extern "C" void kernel_launch(void* const* d_in, const int* in_sizes, int n_in,
                              void* d_out, int out_size)
{
    (void)in_sizes; (void)n_in; (void)out_size;
    const float* x1   = (const float*)d_in[0];
    const float* x2   = (const float*)d_in[1];
    const float* w    = (const float*)d_in[2];
    const float* mask = (const float*)d_in[3];
    float* out        = (float*)d_out;

    const int SM_M1 = (384 * 136 + 16 * 32 * 4) * 4;              // 217088
    const int SM_T1 = (128 * 128 + 4 * 8 * 1 * 136) * 4;          //  82944
    const int SM_T3 = (128 * 128 + 4 * 8 * 3 * 136) * 4;          // 117760
    const int SM_T5 = (128 * 128 + 4 * 8 * 5 * 136) * 4;          // 152576
    const int SM_T7 = (128 * 128 + 4 * 8 * 7 * 136) * 4;          // 187392

    cudaFuncSetAttribute(mode1_mma,
                         cudaFuncAttributeMaxDynamicSharedMemorySize, SM_M1);
    cudaFuncSetAttribute(tc_group<1, false>,
                         cudaFuncAttributeMaxDynamicSharedMemorySize, SM_T1);
    cudaFuncSetAttribute(tc_group<3, true>,
                         cudaFuncAttributeMaxDynamicSharedMemorySize, SM_T3);
    cudaFuncSetAttribute(tc_group<5, true>,
                         cudaFuncAttributeMaxDynamicSharedMemorySize, SM_T5);
    cudaFuncSetAttribute(tc_group<7, true>,
                         cudaFuncAttributeMaxDynamicSharedMemorySize, SM_T7);

    const int GRID = 148;

    // mode-1 first; consumers right after (g_mixed L2 residency), tc1 last.
    mode1_mma<<<GRID, 256, SM_M1>>>(x2, w);

    tc_group<3, true><<<GRID, 512, SM_T3>>>(
        x1, x2, w, mask, out, 128, 128, 128, 512, 1 * 16384, 0, C_INV3);
    tc_group<5, true><<<GRID, 512, SM_T5>>>(
        x1, x2, w, mask, out, 512, 512, 256, 896, 2 * 16384, 128, C_INV5);
    tc_group<7, true><<<GRID, 512, SM_T7>>>(
        x1, x2, w, mask, out, 1152, 1152, 384, 1536, 3 * 16384, 256, C_INV7);
    tc_group<1, false><<<GRID, 512, SM_T1>>>(
        x1, x2, w, mask, out, 0, 0, 0, 0, 0 * 16384, 0, 1.0f);
}

// round 9
// speedup vs baseline: 1.2801x; 1.2801x over previous
#include <cuda_runtime.h>
#include <cstdint>

#define NB      32768
#define IN_DIM  2048
#define OUT_DIM 2432

#define C_INV3 0.57735026918962576451f
#define C_INV5 0.44721359549995793928f
#define C_INV7 0.37796447300922722721f

// Scratch for mode-1 mixed factors: [NB][384], pre-scaled by 1/sqrt(d).
__device__ float g_mixed[(size_t)NB * 384];

// ---------------- tf32 mma.sync helpers (base sm_103) ----------------
__device__ __forceinline__ uint32_t cvt_tf32(float x) {
    uint32_t r; asm("cvt.rna.tf32.f32 %0, %1;" : "=r"(r) : "f"(x)); return r;
}
__device__ __forceinline__ void mma_tf32(float c[4], const uint32_t a[4],
                                         uint32_t b0, uint32_t b1) {
    asm volatile(
        "mma.sync.aligned.m16n8k8.row.col.f32.tf32.tf32.f32 "
        "{%0,%1,%2,%3}, {%4,%5,%6,%7}, {%8,%9}, {%0,%1,%2,%3};"
        : "+f"(c[0]), "+f"(c[1]), "+f"(c[2]), "+f"(c[3])
        : "r"(a[0]), "r"(a[1]), "r"(a[2]), "r"(a[3]), "r"(b0), "r"(b1));
}
__device__ __forceinline__ void bar_g(int id) {
    asm volatile("bar.sync %0, 128;" :: "r"(id) : "memory");
}

// ---------------------------------------------------------------------------
// mode-1 GEMM: g_mixed[b, u'] = sum_v x2[b,v] * W'[u',v] * scale(u')
//   A = x2 tile [16 t][128 v] (row-major, pitch 132), register double-buffered
//   B = stacked scaled W' [384 u'][128 v], XOR-swizzled, no pad (196KB smem)
// ---------------------------------------------------------------------------
__global__ void __launch_bounds__(256, 1)
mode1_mma(const float* __restrict__ x2, const float* __restrict__ weight)
{
    extern __shared__ float sm[];
    uint32_t* Wb  = (uint32_t*)sm;          // [384][128] swizzled
    float*    x2s = sm + 384 * 128;         // [16][132]
    uint32_t* x2u = (uint32_t*)x2s;

    const int tid  = threadIdx.x;
    const int lane = tid & 31;
    const int warp = tid >> 5;
    const int gid  = lane >> 2;
    const int tig  = lane & 3;

    // Build W' (scaled, tf32, swizzled). Once.
    for (int f = tid; f < 384 * 32; f += 256) {
        int u = f >> 5, q = f & 31;
        int p = u >> 7;
        float sc = (p == 0) ? C_INV3 : ((p == 1) ? C_INV5 : C_INV7);
        float4 w4 = ((const float4*)(weight + 4 * 16384))[f];
        float c[4] = {w4.x * sc, w4.y * sc, w4.z * sc, w4.w * sc};
        int sw = (u & 7) << 2;
        #pragma unroll
        for (int j = 0; j < 4; j++)
            Wb[u * 128 + ((4 * q + j) ^ sw)] = cvt_tf32(c[j]);
    }
    __syncthreads();

    const int n_base = warp * 48;
    const int t0 = tid >> 5, t1 = (tid + 256) >> 5;  // rows for the 2 frags
    const int q0 = tid & 31, q1 = q0;                // col-quad (same)

    float4 pre[2];
    auto load_tile = [&](int b0) {
        pre[0] = __ldg((const float4*)(x2 + (size_t)(b0 + t0) * IN_DIM) + q0);
        pre[1] = __ldg((const float4*)(x2 + (size_t)(b0 + t1) * IN_DIM) + q1);
    };

    int s = blockIdx.x;
    const int sstep = gridDim.x;
    if (s < NB / 16) load_tile(s * 16);

    for (; s < NB / 16; s += sstep) {
        const int b0 = s * 16;
        // Store prefetched A tile (tf32), vectorized STS.
        {
            uint4 o0, o1;
            o0.x = cvt_tf32(pre[0].x); o0.y = cvt_tf32(pre[0].y);
            o0.z = cvt_tf32(pre[0].z); o0.w = cvt_tf32(pre[0].w);
            o1.x = cvt_tf32(pre[1].x); o1.y = cvt_tf32(pre[1].y);
            o1.z = cvt_tf32(pre[1].z); o1.w = cvt_tf32(pre[1].w);
            *(uint4*)(x2u + t0 * 132 + 4 * q0) = o0;
            *(uint4*)(x2u + t1 * 132 + 4 * q1) = o1;
        }
        __syncthreads();

        float acc[6][4];
        #pragma unroll
        for (int nt = 0; nt < 6; nt++)
            #pragma unroll
            for (int j = 0; j < 4; j++) acc[nt][j] = 0.0f;

        #pragma unroll
        for (int s16 = 0; s16 < 16; s16++) {
            const int v0 = 8 * s16;
            uint32_t a[4];
            a[0] = x2u[(gid    ) * 132 + v0 + tig    ];
            a[1] = x2u[(gid + 8) * 132 + v0 + tig    ];
            a[2] = x2u[(gid    ) * 132 + v0 + tig + 4];
            a[3] = x2u[(gid + 8) * 132 + v0 + tig + 4];
            #pragma unroll
            for (int nt = 0; nt < 6; nt++) {
                int ur = n_base + nt * 8 + gid;
                int sw = (ur & 7) << 2;
                uint32_t b0r = Wb[ur * 128 + ((v0 + tig    ) ^ sw)];
                uint32_t b1r = Wb[ur * 128 + ((v0 + tig + 4) ^ sw)];
                mma_tf32(acc[nt], a, b0r, b1r);
            }
        }

        // Prefetch next tile while dump stores drain.
        if (s + sstep < NB / 16) load_tile((s + sstep) * 16);

        // Dump straight to gmem: c0,c1 -> row b0+gid; c2,c3 -> row b0+gid+8.
        #pragma unroll
        for (int nt = 0; nt < 6; nt++) {
            int n0 = n_base + nt * 8 + 2 * tig;
            float2 lo; lo.x = acc[nt][0]; lo.y = acc[nt][1];
            float2 hi; hi.x = acc[nt][2]; hi.y = acc[nt][3];
            *(float2*)(g_mixed + (size_t)(b0 + gid    ) * 384 + n0) = lo;
            *(float2*)(g_mixed + (size_t)(b0 + gid + 8) * 384 + n0) = hi;
        }
        __syncthreads();   // A-tile reads done before next build
    }
}

// ---------------------------------------------------------------------------
// tc_group: 512 threads = 4 independent 128-thread pipelines (named barriers).
// Group g processes 8-row subtiles; GEMM M=128(u) x K=128(v) x N=8D(n=t*D+k):
//   tmp[u,n] = sum_v W[u,v] * x2[b0+t, in2s+v*D+k]
// B tile and accumulator dump share one [8D][132] buffer (aliased).
// PFQ: full register double-buffering of the x2 tile (2D float4 per thread).
// ---------------------------------------------------------------------------
template<int D, bool HAS_M1, bool PFQ>
__global__ void __launch_bounds__(512, 1)
tc_group(const float* __restrict__ x1, const float* __restrict__ x2,
         const float* __restrict__ weight, const float* __restrict__ mask,
         float* __restrict__ out,
         int in1s, int in2s, int outs0, int outs1, int ws0, int moff,
         float inv_d)
{
    constexpr int N  = 8 * D;
    constexpr int PW = 132;
    constexpr int NTILES = NB / 8;

    extern __shared__ float sm[];
    uint32_t* Wu = (uint32_t*)sm;                       // [128][PW]

    const int tid  = threadIdx.x;
    const int g    = tid >> 7;                          // group 0..3
    const int gt   = tid & 127;
    const int lane = tid & 31;
    const int wg   = (tid >> 5) & 3;                    // m-warp in group
    const int gid  = lane >> 2;
    const int tig  = lane & 3;
    const int bar  = g + 1;

    float*    BT  = sm + 128 * PW + g * (N * PW);       // aliased B/Ts buffer
    uint32_t* BTu = (uint32_t*)BT;

    // Build Ws (tf32, pitch 132). Once, all 512 threads.
    for (int f = tid; f < 128 * 32; f += 512) {
        int u = f >> 5, q = f & 31;
        float4 w4 = ((const float4*)(weight + ws0))[f];
        uint4 o;
        o.x = cvt_tf32(w4.x); o.y = cvt_tf32(w4.y);
        o.z = cvt_tf32(w4.z); o.w = cvt_tf32(w4.w);
        *(uint4*)(Wu + u * PW + 4 * q) = o;
    }
    __syncthreads();

    float4 pre[PFQ ? 2 * D : 1];
    auto load_tile = [&](int b0) {
        #pragma unroll
        for (int i = 0; i < 2 * D; i++) {
            int f = gt + 128 * i;
            int t = f / (32 * D);
            int q = f - t * (32 * D);
            pre[i] = __ldg((const float4*)(x2 + (size_t)(b0 + t) * IN_DIM + in2s) + q);
        }
    };

    int s = blockIdx.x * 4 + g;
    const int sstep = gridDim.x * 4;
    if (PFQ && s < NTILES) load_tile(s * 8);

    for (; s < NTILES; s += sstep) {
        const int b0 = s * 8;

        // ---- build B: BT[t*D+k][v] = tf32(x2[b0+t, in2s + v*D + k]) ----
        #pragma unroll
        for (int i = 0; i < 2 * D; i++) {
            int f = gt + 128 * i;
            int t = f / (32 * D);
            int q = f - t * (32 * D);
            float4 v4;
            if (PFQ) v4 = pre[i];
            else v4 = __ldg((const float4*)(x2 + (size_t)(b0 + t) * IN_DIM + in2s) + q);
            float c[4] = {v4.x, v4.y, v4.z, v4.w};
            int e = 4 * q;
            #pragma unroll
            for (int j = 0; j < 4; j++) {
                int v = (e + j) / D, k = (e + j) % D;
                BTu[(t * D + k) * PW + v] = cvt_tf32(c[j]);
            }
        }
        bar_g(bar);

        // ---- MMA: 16 K-steps of k=8 ----
        float acc[2][D][4];
        #pragma unroll
        for (int mt = 0; mt < 2; mt++)
            #pragma unroll
            for (int nt = 0; nt < D; nt++)
                #pragma unroll
                for (int j = 0; j < 4; j++) acc[mt][nt][j] = 0.0f;

        #pragma unroll
        for (int s16 = 0; s16 < 16; s16++) {
            const int v0 = 8 * s16;
            uint32_t a[2][4];
            #pragma unroll
            for (int mt = 0; mt < 2; mt++) {
                int u0 = wg * 32 + mt * 16;
                a[mt][0] = Wu[(u0 + gid    ) * PW + v0 + tig    ];
                a[mt][1] = Wu[(u0 + gid + 8) * PW + v0 + tig    ];
                a[mt][2] = Wu[(u0 + gid    ) * PW + v0 + tig + 4];
                a[mt][3] = Wu[(u0 + gid + 8) * PW + v0 + tig + 4];
            }
            #pragma unroll
            for (int nt = 0; nt < D; nt++) {
                uint32_t b0r = BTu[(nt * 8 + gid) * PW + v0 + tig    ];
                uint32_t b1r = BTu[(nt * 8 + gid) * PW + v0 + tig + 4];
                mma_tf32(acc[0][nt], a[0], b0r, b1r);
                mma_tf32(acc[1][nt], a[1], b0r, b1r);
            }
        }
        bar_g(bar);          // all 4 warps done reading B

        // ---- prefetch next tile (overlaps dump + epilogue + barriers) ----
        if (PFQ && (s + sstep < NTILES)) load_tile((s + sstep) * 8);

        // ---- dump accums into the same buffer as Ts[n][u] ----
        #pragma unroll
        for (int mt = 0; mt < 2; mt++) {
            int ub = wg * 32 + mt * 16 + gid;
            #pragma unroll
            for (int nt = 0; nt < D; nt++) {
                int n0 = nt * 8 + 2 * tig;
                BT[(n0    ) * PW + ub    ] = acc[mt][nt][0];
                BT[(n0 + 1) * PW + ub    ] = acc[mt][nt][1];
                BT[(n0    ) * PW + ub + 8] = acc[mt][nt][2];
                BT[(n0 + 1) * PW + ub + 8] = acc[mt][nt][3];
            }
        }
        bar_g(bar);

        // ---- vectorized epilogue: warp wg handles t = p*4+wg, lane owns 4u ----
        #pragma unroll
        for (int p = 0; p < 2; p++) {
            const int t = p * 4 + wg;
            const size_t b = (size_t)(b0 + t);

            float xv[4 * D];       // xv[uj*D + k]
            float tv[4 * D];       // tv[k*4 + uj]
            const float4* x1p =
                (const float4*)(x1 + b * IN_DIM + in1s + (size_t)4 * lane * D);
            #pragma unroll
            for (int q = 0; q < D; q++) {
                float4 t4 = __ldg(x1p + q);
                xv[4 * q + 0] = t4.x; xv[4 * q + 1] = t4.y;
                xv[4 * q + 2] = t4.z; xv[4 * q + 3] = t4.w;
            }
            #pragma unroll
            for (int k = 0; k < D; k++) {
                float4 t4 = *(const float4*)(BT + (t * D + k) * PW + 4 * lane);
                tv[4 * k + 0] = t4.x; tv[4 * k + 1] = t4.y;
                tv[4 * k + 2] = t4.z; tv[4 * k + 3] = t4.w;
            }

            float m4[4] = {0.0f, 0.0f, 0.0f, 0.0f};
            #pragma unroll
            for (int uj = 0; uj < 4; uj++)
                #pragma unroll
                for (int k = 0; k < D; k++)
                    m4[uj] = fmaf(xv[uj * D + k], tv[4 * k + uj], m4[uj]);

            {
                float4 mk = __ldg((const float4*)(mask + outs0) + lane);
                float4 o;
                o.x = m4[0] * inv_d * mk.x; o.y = m4[1] * inv_d * mk.y;
                o.z = m4[2] * inv_d * mk.z; o.w = m4[3] * inv_d * mk.w;
                *(float4*)(out + b * OUT_DIM + outs0 + 4 * lane) = o;
            }

            if (HAS_M1) {
                float4 mx = __ldg((const float4*)(g_mixed + b * 384 + moff) + lane);
                float mix[4] = {mx.x, mx.y, mx.z, mx.w};
                const float4* mk1 =
                    (const float4*)(mask + outs1 + (size_t)4 * lane * D);
                float4* op = (float4*)(out + b * OUT_DIM + outs1 + (size_t)4 * lane * D);
                #pragma unroll
                for (int q = 0; q < D; q++) {
                    float4 mq = __ldg(mk1 + q);
                    float4 o;
                    o.x = xv[4 * q + 0] * mix[(4 * q + 0) / D] * mq.x;
                    o.y = xv[4 * q + 1] * mix[(4 * q + 1) / D] * mq.y;
                    o.z = xv[4 * q + 2] * mix[(4 * q + 2) / D] * mq.z;
                    o.w = xv[4 * q + 3] * mix[(4 * q + 3) / D] * mq.w;
                    op[q] = o;
                }
            }
        }
        bar_g(bar);          // Ts reads done before next build overwrites
    }
}

// ---------------------------------------------------------------------------
extern "C" void kernel_launch(void* const* d_in, const int* in_sizes, int n_in,
                              void* d_out, int out_size)
{
    (void)in_sizes; (void)n_in; (void)out_size;
    const float* x1   = (const float*)d_in[0];
    const float* x2   = (const float*)d_in[1];
    const float* w    = (const float*)d_in[2];
    const float* mask = (const float*)d_in[3];
    float* out        = (float*)d_out;

    const int SM_M1 = (384 * 128 + 16 * 132) * 4;                 // 205056
    const int SM_T1 = (128 * 132 + 4 * 8 * 1 * 132) * 4;          //  84480
    const int SM_T3 = (128 * 132 + 4 * 8 * 3 * 132) * 4;          // 118272
    const int SM_T5 = (128 * 132 + 4 * 8 * 5 * 132) * 4;          // 152064
    const int SM_T7 = (128 * 132 + 4 * 8 * 7 * 132) * 4;          // 185856

    cudaFuncSetAttribute(mode1_mma,
                         cudaFuncAttributeMaxDynamicSharedMemorySize, SM_M1);
    cudaFuncSetAttribute(tc_group<1, false, true>,
                         cudaFuncAttributeMaxDynamicSharedMemorySize, SM_T1);
    cudaFuncSetAttribute(tc_group<3, true, true>,
                         cudaFuncAttributeMaxDynamicSharedMemorySize, SM_T3);
    cudaFuncSetAttribute(tc_group<5, true, true>,
                         cudaFuncAttributeMaxDynamicSharedMemorySize, SM_T5);
    cudaFuncSetAttribute(tc_group<7, true, false>,
                         cudaFuncAttributeMaxDynamicSharedMemorySize, SM_T7);

    const int GRID = 148;

    // mode-1 first (paths 3/5/7 consume g_mixed; same-stream ordering).
    mode1_mma<<<GRID, 256, SM_M1>>>(x2, w);

    tc_group<1, false, true><<<GRID, 512, SM_T1>>>(
        x1, x2, w, mask, out, 0, 0, 0, 0, 0 * 16384, 0, 1.0f);
    tc_group<3, true, true><<<GRID, 512, SM_T3>>>(
        x1, x2, w, mask, out, 128, 128, 128, 512, 1 * 16384, 0, C_INV3);
    tc_group<5, true, true><<<GRID, 512, SM_T5>>>(
        x1, x2, w, mask, out, 512, 512, 256, 896, 2 * 16384, 128, C_INV5);
    tc_group<7, true, false><<<GRID, 512, SM_T7>>>(
        x1, x2, w, mask, out, 1152, 1152, 384, 1536, 3 * 16384, 256, C_INV7);
}